// round 1
// baseline (speedup 1.0000x reference)
#include <cuda_runtime.h>
#include <math.h>

// Problem constants (fixed by reference)
#define NN   100000
#define EE   1600000
#define FIN  256
#define FH   256
#define FOUT 16
#define MPAD 100096   // 782 * 128, padded row count for GEMM tiling

// ---------------------------------------------------------------------------
// Scratch (static __device__ globals; no allocation at runtime)
// ---------------------------------------------------------------------------
__device__ float g_bufA[(size_t)MPAD * 256];   // ~102 MB
__device__ float g_bufB[(size_t)MPAD * 256];   // ~102 MB
__device__ int   g_deg[NN];
__device__ float g_dinv[NN];
__device__ int   g_rowptr[NN + 1];
__device__ int   g_cursor[NN];
__device__ int   g_bsum[128];
__device__ int   g_srcs[EE];
__device__ float g_norms[EE];

__device__ __forceinline__ float* buf_sel(int sel) {
    return (sel == 0) ? g_bufA : g_bufB;
}

// ---------------------------------------------------------------------------
// 1) zero degree + cursor
// ---------------------------------------------------------------------------
__global__ void k_zero() {
    int i = blockIdx.x * blockDim.x + threadIdx.x;
    if (i < NN) { g_deg[i] = 0; g_cursor[i] = 0; }
}

// 2) in-degree histogram over dst
__global__ void k_hist(const int* __restrict__ ei) {
    int e = blockIdx.x * blockDim.x + threadIdx.x;
    if (e < EE) atomicAdd(&g_deg[ei[EE + e]], 1);
}

// 3a) per-block exclusive scan of degrees (block = 1024 elems), also dinv
__global__ void k_scan1() {
    __shared__ int sh[1024];
    int i = blockIdx.x * 1024 + threadIdx.x;
    int v = (i < NN) ? g_deg[i] : 0;
    if (i < NN) g_dinv[i] = rsqrtf((float)v + 1.0f);
    sh[threadIdx.x] = v;
    __syncthreads();
    #pragma unroll
    for (int off = 1; off < 1024; off <<= 1) {
        int t = (threadIdx.x >= off) ? sh[threadIdx.x - off] : 0;
        __syncthreads();
        sh[threadIdx.x] += t;
        __syncthreads();
    }
    if (i < NN) g_rowptr[i] = sh[threadIdx.x] - v;       // exclusive within block
    if (threadIdx.x == 1023) g_bsum[blockIdx.x] = sh[1023];
}

// 3b) scan the 98 block sums (single block)
__global__ void k_scan2() {
    __shared__ int sh[128];
    const int NB = (NN + 1023) / 1024;                   // 98
    int v = (threadIdx.x < NB) ? g_bsum[threadIdx.x] : 0;
    sh[threadIdx.x] = v;
    __syncthreads();
    #pragma unroll
    for (int off = 1; off < 128; off <<= 1) {
        int t = (threadIdx.x >= off) ? sh[threadIdx.x - off] : 0;
        __syncthreads();
        sh[threadIdx.x] += t;
        __syncthreads();
    }
    g_bsum[threadIdx.x] = sh[threadIdx.x] - v;           // exclusive block offsets
}

// 3c) add block offsets -> final exclusive row_ptr
__global__ void k_scan3() {
    int i = blockIdx.x * 1024 + threadIdx.x;
    if (i < NN) g_rowptr[i] += g_bsum[blockIdx.x];
    if (i == 0) g_rowptr[NN] = EE;
}

// 4) scatter edges into CSR order (by dst), precompute norm = dinv[s]*dinv[d]
__global__ void k_scatter(const int* __restrict__ ei) {
    int e = blockIdx.x * blockDim.x + threadIdx.x;
    if (e >= EE) return;
    int s = ei[e];
    int d = ei[EE + e];
    int pos = g_rowptr[d] + atomicAdd(&g_cursor[d], 1);
    g_srcs[pos]  = s;
    g_norms[pos] = g_dinv[s] * g_dinv[d];
}

// ---------------------------------------------------------------------------
// SGEMM: C[M x 256] = A[M x 256] @ W[256 x 256]   (fp32, 128x128x8 tiling)
// asel: 0 -> external pointer (x input), 1 -> g_bufA, 2 -> g_bufB
// ---------------------------------------------------------------------------
__global__ void __launch_bounds__(256) k_gemm256(
    const float* __restrict__ Aext, int asel,
    const float* __restrict__ W, int csel)
{
    const int K = 256;
    const float* __restrict__ A = (asel == 0) ? Aext : ((asel == 1) ? g_bufA : g_bufB);
    float* __restrict__ C = buf_sel(csel);

    __shared__ float As[8][128];
    __shared__ float Bs[8][128];

    const int block_row = blockIdx.x * 128;
    const int block_col = blockIdx.y * 128;
    const int tid  = threadIdx.x;
    const int arow = tid >> 1;            // 0..127
    const int acol = (tid & 1) * 4;       // 0 or 4
    const int brow = tid >> 5;            // 0..7
    const int bcol = (tid & 31) * 4;      // 0..124
    const int tr = (tid >> 4) * 8;        // 0..120
    const int tc = (tid & 15) * 8;        // 0..120

    float acc[8][8];
    #pragma unroll
    for (int i = 0; i < 8; i++)
        #pragma unroll
        for (int j = 0; j < 8; j++) acc[i][j] = 0.0f;

    const int gr = block_row + arow;
    for (int k0 = 0; k0 < K; k0 += 8) {
        float4 av;
        if (gr < NN) av = *(const float4*)(A + (size_t)gr * K + k0 + acol);
        else         av = make_float4(0.f, 0.f, 0.f, 0.f);
        As[acol + 0][arow] = av.x;
        As[acol + 1][arow] = av.y;
        As[acol + 2][arow] = av.z;
        As[acol + 3][arow] = av.w;

        float4 bv = *(const float4*)(W + (size_t)(k0 + brow) * 256 + block_col + bcol);
        *(float4*)&Bs[brow][bcol] = bv;
        __syncthreads();

        #pragma unroll
        for (int k = 0; k < 8; k++) {
            float ra[8], rb[8];
            #pragma unroll
            for (int i = 0; i < 8; i++) ra[i] = As[k][tr + i];
            #pragma unroll
            for (int j = 0; j < 8; j++) rb[j] = Bs[k][tc + j];
            #pragma unroll
            for (int i = 0; i < 8; i++)
                #pragma unroll
                for (int j = 0; j < 8; j++) acc[i][j] += ra[i] * rb[j];
        }
        __syncthreads();
    }

    #pragma unroll
    for (int i = 0; i < 8; i++) {
        int orow = block_row + tr + i;
        if (orow < NN) {
            #pragma unroll
            for (int j = 0; j < 8; j += 4) {
                *(float4*)(C + (size_t)orow * 256 + block_col + tc + j) =
                    make_float4(acc[i][j], acc[i][j + 1], acc[i][j + 2], acc[i][j + 3]);
            }
        }
    }
}

// ---------------------------------------------------------------------------
// SpMM (F=256): out[n] = sum_e norm * H[src] + dinv^2 * H[n] + bias, opt relu
// one warp per node; lane covers float4 at [lane] and [lane+32] of the row
// ---------------------------------------------------------------------------
__global__ void __launch_bounds__(256) k_spmm256(
    int hsel, const float* __restrict__ bias, int osel, int relu)
{
    const float* __restrict__ H = buf_sel(hsel);
    float* __restrict__ O = buf_sel(osel);

    int warp = threadIdx.x >> 5;
    int lane = threadIdx.x & 31;
    int node = blockIdx.x * 8 + warp;
    if (node >= NN) return;

    int beg = g_rowptr[node];
    int end = g_rowptr[node + 1];

    float4 acc0 = make_float4(0.f, 0.f, 0.f, 0.f);
    float4 acc1 = make_float4(0.f, 0.f, 0.f, 0.f);

    for (int e = beg; e < end; e++) {
        int   s = g_srcs[e];
        float w = g_norms[e];
        const float4* hp = (const float4*)(H + (size_t)s * 256);
        float4 a = hp[lane];
        float4 b = hp[lane + 32];
        acc0.x += w * a.x; acc0.y += w * a.y; acc0.z += w * a.z; acc0.w += w * a.w;
        acc1.x += w * b.x; acc1.y += w * b.y; acc1.z += w * b.z; acc1.w += w * b.w;
    }

    // self-loop
    float di = g_dinv[node];
    float w2 = di * di;
    {
        const float4* hp = (const float4*)(H + (size_t)node * 256);
        float4 a = hp[lane];
        float4 b = hp[lane + 32];
        acc0.x += w2 * a.x; acc0.y += w2 * a.y; acc0.z += w2 * a.z; acc0.w += w2 * a.w;
        acc1.x += w2 * b.x; acc1.y += w2 * b.y; acc1.z += w2 * b.z; acc1.w += w2 * b.w;
    }

    const float4* bb = (const float4*)bias;
    float4 b0 = bb[lane];
    float4 b1 = bb[lane + 32];
    acc0.x += b0.x; acc0.y += b0.y; acc0.z += b0.z; acc0.w += b0.w;
    acc1.x += b1.x; acc1.y += b1.y; acc1.z += b1.z; acc1.w += b1.w;

    if (relu) {
        acc0.x = fmaxf(acc0.x, 0.f); acc0.y = fmaxf(acc0.y, 0.f);
        acc0.z = fmaxf(acc0.z, 0.f); acc0.w = fmaxf(acc0.w, 0.f);
        acc1.x = fmaxf(acc1.x, 0.f); acc1.y = fmaxf(acc1.y, 0.f);
        acc1.z = fmaxf(acc1.z, 0.f); acc1.w = fmaxf(acc1.w, 0.f);
    }

    float4* op = (float4*)(O + (size_t)node * 256);
    op[lane]      = acc0;
    op[lane + 32] = acc1;
}

// ---------------------------------------------------------------------------
// GEMM (N=16): C[M x 16] = A[M x 256] @ W[256 x 16]
// ---------------------------------------------------------------------------
__global__ void __launch_bounds__(256) k_gemm16(int asel, const float* __restrict__ W, int csel)
{
    __shared__ float Ws[256 * 16];
    const float* __restrict__ A = buf_sel(asel);
    float* __restrict__ C = buf_sel(csel);

    for (int i = threadIdx.x; i < 256 * 16; i += 256) Ws[i] = W[i];
    __syncthreads();

    int r = blockIdx.x * 16 + (threadIdx.x >> 4);
    int c = threadIdx.x & 15;
    if (r >= NN) return;

    const float4* ar = (const float4*)(A + (size_t)r * 256);
    float acc = 0.f;
    #pragma unroll
    for (int k4 = 0; k4 < 64; k4++) {
        float4 a = ar[k4];
        int k = k4 * 4;
        acc += a.x * Ws[(k + 0) * 16 + c];
        acc += a.y * Ws[(k + 1) * 16 + c];
        acc += a.z * Ws[(k + 2) * 16 + c];
        acc += a.w * Ws[(k + 3) * 16 + c];
    }
    C[(size_t)r * 16 + c] = acc;
}

// ---------------------------------------------------------------------------
// SpMM (F=16) + bias + log_softmax -> final output
// warp per node; feature = lane & 15 (lanes 16..31 mirror for simplicity)
// ---------------------------------------------------------------------------
__global__ void __launch_bounds__(256) k_spmm16(
    int hsel, const float* __restrict__ bias, float* __restrict__ out)
{
    const float* __restrict__ H = buf_sel(hsel);

    int warp = threadIdx.x >> 5;
    int lane = threadIdx.x & 31;
    int node = blockIdx.x * 8 + warp;
    if (node >= NN) return;

    int f = lane & 15;
    int beg = g_rowptr[node];
    int end = g_rowptr[node + 1];

    float acc = 0.f;
    for (int e = beg; e < end; e++) {
        int s = g_srcs[e];
        acc += g_norms[e] * H[(size_t)s * 16 + f];
    }
    float di = g_dinv[node];
    acc += di * di * H[(size_t)node * 16 + f];
    acc += bias[f];

    // log_softmax over the 16 features (width-16 butterfly)
    float m = acc;
    #pragma unroll
    for (int o = 8; o > 0; o >>= 1)
        m = fmaxf(m, __shfl_xor_sync(0xffffffffu, m, o, 16));
    float ex = expf(acc - m);
    float s = ex;
    #pragma unroll
    for (int o = 8; o > 0; o >>= 1)
        s += __shfl_xor_sync(0xffffffffu, s, o, 16);

    if (lane < 16)
        out[(size_t)node * 16 + f] = (acc - m) - logf(s);
}

// ---------------------------------------------------------------------------
// Launcher
// ---------------------------------------------------------------------------
extern "C" void kernel_launch(void* const* d_in, const int* in_sizes, int n_in,
                              void* d_out, int out_size)
{
    const float* x  = (const float*)d_in[0];
    const int*   ei = (const int*)  d_in[1];
    const float* W1 = (const float*)d_in[2];
    const float* b1 = (const float*)d_in[3];
    const float* W2 = (const float*)d_in[4];
    const float* b2 = (const float*)d_in[5];
    const float* W3 = (const float*)d_in[6];
    const float* b3 = (const float*)d_in[7];
    const float* W4 = (const float*)d_in[8];
    const float* b4 = (const float*)d_in[9];
    float* out = (float*)d_out;

    const int NB_SCAN = (NN + 1023) / 1024;   // 98

    // graph preprocessing: degree -> dinv -> CSR(by dst) -> norms
    k_zero   <<<(NN + 255) / 256, 256>>>();
    k_hist   <<<(EE + 255) / 256, 256>>>(ei);
    k_scan1  <<<NB_SCAN, 1024>>>();
    k_scan2  <<<1, 128>>>();
    k_scan3  <<<NB_SCAN, 1024>>>();
    k_scatter<<<(EE + 255) / 256, 256>>>(ei);

    dim3 ggrid((MPAD + 127) / 128, 2);        // 782 x 2
    int  sgrid = (NN + 7) / 8;                // 12500

    // layer 1: x @ W1 -> A ; spmm(A)+b1, relu -> B
    k_gemm256<<<ggrid, 256>>>(x, 0, W1, 0);
    k_spmm256<<<sgrid, 256>>>(0, b1, 1, 1);

    // layer 2: B @ W2 -> A ; spmm -> B
    k_gemm256<<<ggrid, 256>>>(nullptr, 2, W2, 0);
    k_spmm256<<<sgrid, 256>>>(0, b2, 1, 1);

    // layer 3: B @ W3 -> A ; spmm -> B
    k_gemm256<<<ggrid, 256>>>(nullptr, 2, W3, 0);
    k_spmm256<<<sgrid, 256>>>(0, b3, 1, 1);

    // layer 4: B @ W4 -> A (16 wide) ; spmm + log_softmax -> out
    k_gemm16 <<<(NN + 15) / 16, 256>>>(1, W4, 0);
    k_spmm16 <<<sgrid, 256>>>(0, b4, out);
}

// round 3
// speedup vs baseline: 1.4831x; 1.4831x over previous
#include <cuda_runtime.h>
#include <cuda_bf16.h>
#include <math.h>
#include <stdint.h>

// Problem constants (fixed by reference)
#define NN   100000
#define EE   1600000
#define MPAD 100096   // 782 * 128

// ---------------------------------------------------------------------------
// Scratch (__device__ globals; no runtime allocation)
// ---------------------------------------------------------------------------
__device__ float         g_gout[(size_t)MPAD * 256];   // GEMM fp32 output / SpMM input
__device__ __nv_bfloat16 g_ah[(size_t)MPAD * 256];     // activation hi (bf16)
__device__ __nv_bfloat16 g_al[(size_t)MPAD * 256];     // activation lo (bf16)
__device__ __nv_bfloat16 g_wh[3 * 256 * 256];          // W^T hi per layer (n-major, k contig)
__device__ __nv_bfloat16 g_wl[3 * 256 * 256];          // W^T lo per layer
__device__ int   g_deg[NN];
__device__ float g_dinv[NN];
__device__ int   g_rowptr[NN + 1];
__device__ int   g_cursor[NN];
__device__ int   g_bsum[128];
__device__ int   g_srcs[EE];
__device__ float g_norms[EE];

// ---------------------------------------------------------------------------
// PTX helpers (all sm_80-era: valid on plain compute_100 target)
// ---------------------------------------------------------------------------
__device__ __forceinline__ uint32_t smem_u32(const void* p) {
    uint32_t a;
    asm("{ .reg .u64 t; cvta.to.shared.u64 t, %1; cvt.u32.u64 %0, t; }"
        : "=r"(a) : "l"(p));
    return a;
}

#define CP16(smem_addr, gptr) \
    asm volatile("cp.async.cg.shared.global [%0], [%1], 16;" \
        :: "r"(smem_addr), "l"(gptr) : "memory")
#define CP_COMMIT() asm volatile("cp.async.commit_group;" ::: "memory")
#define CP_WAIT1()  asm volatile("cp.async.wait_group 1;" ::: "memory")
#define CP_WAIT0()  asm volatile("cp.async.wait_group 0;" ::: "memory")

#define LDSM4(r0, r1, r2, r3, addr) \
    asm volatile("ldmatrix.sync.aligned.m8n8.x4.shared.b16 {%0,%1,%2,%3}, [%4];" \
        : "=r"(r0), "=r"(r1), "=r"(r2), "=r"(r3) : "r"(addr))

#define MMA16816(d, a, b) \
    asm volatile("mma.sync.aligned.m16n8k16.row.col.f32.bf16.bf16.f32 " \
        "{%0,%1,%2,%3},{%4,%5,%6,%7},{%8,%9},{%0,%1,%2,%3};" \
        : "+f"((d)[0]), "+f"((d)[1]), "+f"((d)[2]), "+f"((d)[3]) \
        : "r"((a)[0]), "r"((a)[1]), "r"((a)[2]), "r"((a)[3]), \
          "r"((b)[0]), "r"((b)[1]))

// ---------------------------------------------------------------------------
// bf16 hi/lo split helper
// ---------------------------------------------------------------------------
__device__ __forceinline__ void split4(float4 v, __nv_bfloat16* ph, __nv_bfloat16* pl) {
    __nv_bfloat162 h0 = __floats2bfloat162_rn(v.x, v.y);
    __nv_bfloat162 h1 = __floats2bfloat162_rn(v.z, v.w);
    float2 f0 = __bfloat1622float2(h0);
    float2 f1 = __bfloat1622float2(h1);
    __nv_bfloat162 l0 = __floats2bfloat162_rn(v.x - f0.x, v.y - f0.y);
    __nv_bfloat162 l1 = __floats2bfloat162_rn(v.z - f1.x, v.w - f1.y);
    *(__nv_bfloat162*)(ph)     = h0;
    *(__nv_bfloat162*)(ph + 2) = h1;
    *(__nv_bfloat162*)(pl)     = l0;
    *(__nv_bfloat162*)(pl + 2) = l1;
}

// ---------------------------------------------------------------------------
// Graph preprocessing
// ---------------------------------------------------------------------------
__global__ void k_zero() {
    int i = blockIdx.x * blockDim.x + threadIdx.x;
    if (i < NN) { g_deg[i] = 0; g_cursor[i] = 0; }
}

__global__ void k_hist(const int* __restrict__ ei) {
    int e = blockIdx.x * blockDim.x + threadIdx.x;
    if (e < EE) atomicAdd(&g_deg[ei[EE + e]], 1);
}

__global__ void k_scan1() {
    __shared__ int sh[1024];
    int i = blockIdx.x * 1024 + threadIdx.x;
    int v = (i < NN) ? g_deg[i] : 0;
    if (i < NN) g_dinv[i] = rsqrtf((float)v + 1.0f);
    sh[threadIdx.x] = v;
    __syncthreads();
    #pragma unroll
    for (int off = 1; off < 1024; off <<= 1) {
        int t = (threadIdx.x >= off) ? sh[threadIdx.x - off] : 0;
        __syncthreads();
        sh[threadIdx.x] += t;
        __syncthreads();
    }
    if (i < NN) g_rowptr[i] = sh[threadIdx.x] - v;
    if (threadIdx.x == 1023) g_bsum[blockIdx.x] = sh[1023];
}

__global__ void k_scan2() {
    __shared__ int sh[128];
    const int NB = (NN + 1023) / 1024;
    int v = (threadIdx.x < NB) ? g_bsum[threadIdx.x] : 0;
    sh[threadIdx.x] = v;
    __syncthreads();
    #pragma unroll
    for (int off = 1; off < 128; off <<= 1) {
        int t = (threadIdx.x >= off) ? sh[threadIdx.x - off] : 0;
        __syncthreads();
        sh[threadIdx.x] += t;
        __syncthreads();
    }
    g_bsum[threadIdx.x] = sh[threadIdx.x] - v;
}

__global__ void k_scan3() {
    int i = blockIdx.x * 1024 + threadIdx.x;
    if (i < NN) g_rowptr[i] += g_bsum[blockIdx.x];
    if (i == 0) g_rowptr[NN] = EE;
}

__global__ void k_scatter(const int* __restrict__ ei) {
    int e = blockIdx.x * blockDim.x + threadIdx.x;
    if (e >= EE) return;
    int s = ei[e];
    int d = ei[EE + e];
    int pos = g_rowptr[d] + atomicAdd(&g_cursor[d], 1);
    g_srcs[pos]  = s;
    g_norms[pos] = g_dinv[s] * g_dinv[d];
}

// ---------------------------------------------------------------------------
// Weight transpose + bf16 split: Wh/Wl[n*256+k] from W[k*256+n]
// ---------------------------------------------------------------------------
__global__ void k_wsplit(const float* __restrict__ W1, const float* __restrict__ W2,
                         const float* __restrict__ W3) {
    int idx = blockIdx.x * 256 + threadIdx.x;   // 0..196607
    int l = idx >> 16;
    int r = idx & 65535;
    int k = r >> 8, n = r & 255;
    const float* W = (l == 0) ? W1 : ((l == 1) ? W2 : W3);
    float v = W[k * 256 + n];
    __nv_bfloat16 hi = __float2bfloat16(v);
    g_wh[l * 65536 + n * 256 + k] = hi;
    g_wl[l * 65536 + n * 256 + k] = __float2bfloat16(v - __bfloat162float(hi));
}

// x (fp32) -> g_ah/g_al (bf16 hi/lo)
__global__ void k_xsplit(const float* __restrict__ x) {
    size_t i = (size_t)blockIdx.x * blockDim.x + threadIdx.x;   // float4 index
    if (i >= (size_t)NN * 64) return;
    float4 v = ((const float4*)x)[i];
    split4(v, g_ah + i * 4, g_al + i * 4);
}

// ---------------------------------------------------------------------------
// Tensor GEMM via mma.sync (bf16 split 3-term):
//   g_gout[M x 256] = (Ah+Al)[M x 256] @ W[256 x 256]
// CTA tile 128x128, 8 warps (4m x 2n), warp tile 32x64, K-step 16,
// cp.async double buffer. SMEM layout (bytes):
//   A: buf*12288 + part*6144 + r*48 + k*2        (128 rows, 16 k, pad->24)
//   B: 24576 + buf*12288 + part*6144 + n*48 + k*2
// ---------------------------------------------------------------------------
#define MG_SMEM 49152

__global__ void __launch_bounds__(256, 2) k_mgemm(int lidx) {
    extern __shared__ char smem[];
    const uint32_t sb = smem_u32(smem);

    const int tid  = threadIdx.x;
    const int wid  = tid >> 5;
    const int lane = tid & 31;
    const int wm   = wid >> 1;          // 0..3
    const int wn   = wid & 1;           // 0..1
    const size_t row0  = (size_t)blockIdx.x * 128;
    const int    ncol0 = blockIdx.y * 128;

    const __nv_bfloat16* __restrict__ Wh = g_wh + (size_t)lidx * 65536;
    const __nv_bfloat16* __restrict__ Wl = g_wl + (size_t)lidx * 65536;

    // global-load thread mapping (per k-step)
    const int gr = tid >> 1;            // 0..127 (row / ncol)
    const int gk = (tid & 1) * 8;       // bf16 k offset within 16
    const size_t gA = (row0 + gr) * 256 + gk;
    const size_t gB = ((size_t)(ncol0 + gr)) * 256 + gk;
    const uint32_t sOff = (uint32_t)(gr * 48 + gk * 2);

    // ldmatrix per-thread offsets
    const int lr = lane & 7;
    const uint32_t offA = (uint32_t)((wm * 32 + lr + ((lane >> 3) & 1) * 8) * 48
                                     + ((lane >> 4) & 1) * 16);
    const uint32_t offB = (uint32_t)((wn * 64 + lr + ((lane >> 4) & 1) * 8) * 48
                                     + ((lane >> 3) & 1) * 16);

    float acc[2][8][4];
    #pragma unroll
    for (int i = 0; i < 2; i++)
        #pragma unroll
        for (int j = 0; j < 8; j++)
            #pragma unroll
            for (int q = 0; q < 4; q++) acc[i][j][q] = 0.f;

    // prologue: load k-step 0 into buffer 0
    {
        uint32_t sa = sb + sOff;
        CP16(sa,         g_ah + gA);
        CP16(sa + 6144,  g_al + gA);
        uint32_t sbf = sb + 24576 + sOff;
        CP16(sbf,        Wh + gB);
        CP16(sbf + 6144, Wl + gB);
        CP_COMMIT();
    }

    for (int c = 0; c < 16; c++) {
        const int buf = c & 1;
        if (c + 1 < 16) {
            const uint32_t bo = (uint32_t)((c + 1) & 1) * 12288u;
            const size_t kk = (size_t)(c + 1) * 16;
            uint32_t sa = sb + bo + sOff;
            CP16(sa,         g_ah + gA + kk);
            CP16(sa + 6144,  g_al + gA + kk);
            uint32_t sbf = sb + 24576 + bo + sOff;
            CP16(sbf,        Wh + gB + kk);
            CP16(sbf + 6144, Wl + gB + kk);
            CP_COMMIT();
            CP_WAIT1();
        } else {
            CP_WAIT0();
        }
        __syncthreads();

        const uint32_t aBase = sb + (uint32_t)buf * 12288u + offA;
        const uint32_t bBase = sb + 24576u + (uint32_t)buf * 12288u + offB;

        uint32_t ah[2][4], al[2][4], bh[8][2], bl[8][2];
        #pragma unroll
        for (int mi = 0; mi < 2; mi++) {
            LDSM4(ah[mi][0], ah[mi][1], ah[mi][2], ah[mi][3], aBase + mi * 768u);
            LDSM4(al[mi][0], al[mi][1], al[mi][2], al[mi][3], aBase + 6144u + mi * 768u);
        }
        #pragma unroll
        for (int j = 0; j < 4; j++) {
            uint32_t t0, t1, t2, t3;
            LDSM4(t0, t1, t2, t3, bBase + j * 768u);
            bh[2 * j][0] = t0; bh[2 * j][1] = t1;
            bh[2 * j + 1][0] = t2; bh[2 * j + 1][1] = t3;
            LDSM4(t0, t1, t2, t3, bBase + 6144u + j * 768u);
            bl[2 * j][0] = t0; bl[2 * j][1] = t1;
            bl[2 * j + 1][0] = t2; bl[2 * j + 1][1] = t3;
        }

        #pragma unroll
        for (int mi = 0; mi < 2; mi++)
            #pragma unroll
            for (int nj = 0; nj < 8; nj++) {
                MMA16816(acc[mi][nj], ah[mi], bh[nj]);
                MMA16816(acc[mi][nj], ah[mi], bl[nj]);
                MMA16816(acc[mi][nj], al[mi], bh[nj]);
            }
        __syncthreads();
    }

    // epilogue
    #pragma unroll
    for (int mi = 0; mi < 2; mi++) {
        const size_t r0 = row0 + wm * 32 + mi * 16 + (lane >> 2);
        const int cc0 = ncol0 + wn * 64 + (lane & 3) * 2;
        #pragma unroll
        for (int nj = 0; nj < 8; nj++) {
            const int cc = cc0 + nj * 8;
            if (r0 < NN)
                *(float2*)&g_gout[r0 * 256 + cc] =
                    make_float2(acc[mi][nj][0], acc[mi][nj][1]);
            if (r0 + 8 < NN)
                *(float2*)&g_gout[(r0 + 8) * 256 + cc] =
                    make_float2(acc[mi][nj][2], acc[mi][nj][3]);
        }
    }
}

// ---------------------------------------------------------------------------
// SpMM (F=256): agg = sum_e norm * H[src] + dinv^2 * H[n] + bias, relu,
// writes bf16 hi/lo splits for the next GEMM. H = g_gout (fp32).
// ---------------------------------------------------------------------------
__global__ void __launch_bounds__(256) k_spmm256(const float* __restrict__ bias) {
    const float* __restrict__ H = g_gout;

    int warp = threadIdx.x >> 5;
    int lane = threadIdx.x & 31;
    int node = blockIdx.x * 8 + warp;
    if (node >= NN) return;

    int beg = g_rowptr[node];
    int end = g_rowptr[node + 1];

    float4 acc0 = make_float4(0.f, 0.f, 0.f, 0.f);
    float4 acc1 = make_float4(0.f, 0.f, 0.f, 0.f);

    int e = beg;
    for (; e + 1 < end; e += 2) {
        int   s0 = g_srcs[e],     s1 = g_srcs[e + 1];
        float w0 = g_norms[e],    w1 = g_norms[e + 1];
        const float4* hp0 = (const float4*)(H + (size_t)s0 * 256);
        const float4* hp1 = (const float4*)(H + (size_t)s1 * 256);
        float4 a0 = hp0[lane];
        float4 b0 = hp0[lane + 32];
        float4 a1 = hp1[lane];
        float4 b1 = hp1[lane + 32];
        acc0.x += w0 * a0.x + w1 * a1.x; acc0.y += w0 * a0.y + w1 * a1.y;
        acc0.z += w0 * a0.z + w1 * a1.z; acc0.w += w0 * a0.w + w1 * a1.w;
        acc1.x += w0 * b0.x + w1 * b1.x; acc1.y += w0 * b0.y + w1 * b1.y;
        acc1.z += w0 * b0.z + w1 * b1.z; acc1.w += w0 * b0.w + w1 * b1.w;
    }
    for (; e < end; e++) {
        int   s = g_srcs[e];
        float w = g_norms[e];
        const float4* hp = (const float4*)(H + (size_t)s * 256);
        float4 a = hp[lane];
        float4 b = hp[lane + 32];
        acc0.x += w * a.x; acc0.y += w * a.y; acc0.z += w * a.z; acc0.w += w * a.w;
        acc1.x += w * b.x; acc1.y += w * b.y; acc1.z += w * b.z; acc1.w += w * b.w;
    }

    float di = g_dinv[node];
    float w2 = di * di;
    {
        const float4* hp = (const float4*)(H + (size_t)node * 256);
        float4 a = hp[lane];
        float4 b = hp[lane + 32];
        acc0.x += w2 * a.x; acc0.y += w2 * a.y; acc0.z += w2 * a.z; acc0.w += w2 * a.w;
        acc1.x += w2 * b.x; acc1.y += w2 * b.y; acc1.z += w2 * b.z; acc1.w += w2 * b.w;
    }

    const float4* bb = (const float4*)bias;
    float4 b0 = bb[lane];
    float4 b1 = bb[lane + 32];
    acc0.x = fmaxf(acc0.x + b0.x, 0.f); acc0.y = fmaxf(acc0.y + b0.y, 0.f);
    acc0.z = fmaxf(acc0.z + b0.z, 0.f); acc0.w = fmaxf(acc0.w + b0.w, 0.f);
    acc1.x = fmaxf(acc1.x + b1.x, 0.f); acc1.y = fmaxf(acc1.y + b1.y, 0.f);
    acc1.z = fmaxf(acc1.z + b1.z, 0.f); acc1.w = fmaxf(acc1.w + b1.w, 0.f);

    size_t base = (size_t)node * 256 + lane * 4;
    split4(acc0, g_ah + base,       g_al + base);
    split4(acc1, g_ah + base + 128, g_al + base + 128);
}

// ---------------------------------------------------------------------------
// GEMM (N=16): g_gout[M x 16] = (g_ah+g_al)[M x 256] @ W4[256 x 16]
// ---------------------------------------------------------------------------
__global__ void __launch_bounds__(256) k_gemm16(const float* __restrict__ W) {
    __shared__ float Ws[256 * 16];
    for (int i = threadIdx.x; i < 256 * 16; i += 256) Ws[i] = W[i];
    __syncthreads();

    int r = blockIdx.x * 16 + (threadIdx.x >> 4);
    int c = threadIdx.x & 15;
    if (r >= NN) return;

    const __nv_bfloat162* ah = (const __nv_bfloat162*)(g_ah + (size_t)r * 256);
    const __nv_bfloat162* al = (const __nv_bfloat162*)(g_al + (size_t)r * 256);
    float acc = 0.f;
    #pragma unroll 16
    for (int k2 = 0; k2 < 128; k2++) {
        float2 h = __bfloat1622float2(ah[k2]);
        float2 l = __bfloat1622float2(al[k2]);
        acc += (h.x + l.x) * Ws[(2 * k2) * 16 + c];
        acc += (h.y + l.y) * Ws[(2 * k2 + 1) * 16 + c];
    }
    g_gout[(size_t)r * 16 + c] = acc;
}

// ---------------------------------------------------------------------------
// SpMM (F=16) + bias + log_softmax -> final output
// ---------------------------------------------------------------------------
__global__ void __launch_bounds__(256) k_spmm16(const float* __restrict__ bias,
                                               float* __restrict__ out) {
    const float* __restrict__ H = g_gout;

    int warp = threadIdx.x >> 5;
    int lane = threadIdx.x & 31;
    int node = blockIdx.x * 8 + warp;
    if (node >= NN) return;

    int f = lane & 15;
    int beg = g_rowptr[node];
    int end = g_rowptr[node + 1];

    float acc = 0.f;
    for (int e = beg; e < end; e++) {
        int s = g_srcs[e];
        acc += g_norms[e] * H[(size_t)s * 16 + f];
    }
    float di = g_dinv[node];
    acc += di * di * H[(size_t)node * 16 + f];
    acc += bias[f];

    float m = acc;
    #pragma unroll
    for (int o = 8; o > 0; o >>= 1)
        m = fmaxf(m, __shfl_xor_sync(0xffffffffu, m, o, 16));
    float ex = expf(acc - m);
    float s = ex;
    #pragma unroll
    for (int o = 8; o > 0; o >>= 1)
        s += __shfl_xor_sync(0xffffffffu, s, o, 16);

    if (lane < 16)
        out[(size_t)node * 16 + f] = (acc - m) - logf(s);
}

// ---------------------------------------------------------------------------
// Launcher
// ---------------------------------------------------------------------------
extern "C" void kernel_launch(void* const* d_in, const int* in_sizes, int n_in,
                              void* d_out, int out_size)
{
    const float* x  = (const float*)d_in[0];
    const int*   ei = (const int*)  d_in[1];
    const float* W1 = (const float*)d_in[2];
    const float* b1 = (const float*)d_in[3];
    const float* W2 = (const float*)d_in[4];
    const float* b2 = (const float*)d_in[5];
    const float* W3 = (const float*)d_in[6];
    const float* b3 = (const float*)d_in[7];
    const float* W4 = (const float*)d_in[8];
    const float* b4 = (const float*)d_in[9];
    float* out = (float*)d_out;

    static int s_attr_done = 0;
    if (!s_attr_done) {
        cudaFuncSetAttribute(k_mgemm, cudaFuncAttributeMaxDynamicSharedMemorySize, MG_SMEM);
        s_attr_done = 1;
    }

    const int NB_SCAN = (NN + 1023) / 1024;   // 98

    // graph preprocessing
    k_zero   <<<(NN + 255) / 256, 256>>>();
    k_hist   <<<(EE + 255) / 256, 256>>>(ei);
    k_scan1  <<<NB_SCAN, 1024>>>();
    k_scan2  <<<1, 128>>>();
    k_scan3  <<<NB_SCAN, 1024>>>();
    k_scatter<<<(EE + 255) / 256, 256>>>(ei);

    // operand prep
    k_wsplit <<<768, 256>>>(W1, W2, W3);
    k_xsplit <<<(NN * 64 + 255) / 256, 256>>>(x);

    dim3 ggrid(MPAD / 128, 2);                // 782 x 2
    const int sgrid = (NN + 7) / 8;           // 12500

    // layer 1
    k_mgemm  <<<ggrid, 256, MG_SMEM>>>(0);
    k_spmm256<<<sgrid, 256>>>(b1);
    // layer 2
    k_mgemm  <<<ggrid, 256, MG_SMEM>>>(1);
    k_spmm256<<<sgrid, 256>>>(b2);
    // layer 3
    k_mgemm  <<<ggrid, 256, MG_SMEM>>>(2);
    k_spmm256<<<sgrid, 256>>>(b3);
    // layer 4
    k_gemm16 <<<(NN + 15) / 16, 256>>>(W4);
    k_spmm16 <<<sgrid, 256>>>(b4, out);
}

// round 5
// speedup vs baseline: 1.5276x; 1.0300x over previous
#include <cuda_runtime.h>
#include <cuda_bf16.h>
#include <math.h>
#include <stdint.h>

// Problem constants (fixed by reference)
#define NN   100000
#define EE   1600000
#define MPAD 100096   // 782 * 128

// ---------------------------------------------------------------------------
// Scratch (__device__ globals; no runtime allocation)
// ---------------------------------------------------------------------------
__device__ float         g_gout[(size_t)MPAD * 256];   // GEMM fp32 output / SpMM input
__device__ __nv_bfloat16 g_ah[(size_t)MPAD * 256];     // activation hi (bf16)
__device__ __nv_bfloat16 g_al[(size_t)MPAD * 256];     // activation lo (bf16)
__device__ __nv_bfloat16 g_wh[3 * 256 * 256];          // W^T hi per layer (n-major, k contig)
__device__ __nv_bfloat16 g_wl[3 * 256 * 256];          // W^T lo per layer
__device__ int   g_deg[NN];
__device__ float g_dinv[NN];
__device__ int   g_rowptr[NN + 1];
__device__ int   g_cursor[NN];
__device__ int   g_bsum[128];
__device__ int   g_srcs[EE];
__device__ float g_norms[EE];

// ---------------------------------------------------------------------------
// PTX helpers (sm_80-era; valid on plain compute_100 target)
// ---------------------------------------------------------------------------
__device__ __forceinline__ uint32_t smem_u32(const void* p) {
    uint32_t a;
    asm("{ .reg .u64 t; cvta.to.shared.u64 t, %1; cvt.u32.u64 %0, t; }"
        : "=r"(a) : "l"(p));
    return a;
}

#define CP16(smem_addr, gptr) \
    asm volatile("cp.async.cg.shared.global [%0], [%1], 16;" \
        :: "r"(smem_addr), "l"(gptr) : "memory")
#define CP_COMMIT() asm volatile("cp.async.commit_group;" ::: "memory")
#define CP_WAIT2()  asm volatile("cp.async.wait_group 2;" ::: "memory")

#define LDSM4(r0, r1, r2, r3, addr) \
    asm volatile("ldmatrix.sync.aligned.m8n8.x4.shared.b16 {%0,%1,%2,%3}, [%4];" \
        : "=r"(r0), "=r"(r1), "=r"(r2), "=r"(r3) : "r"(addr))

#define MMA16816(d, a, b) \
    asm volatile("mma.sync.aligned.m16n8k16.row.col.f32.bf16.bf16.f32 " \
        "{%0,%1,%2,%3},{%4,%5,%6,%7},{%8,%9},{%0,%1,%2,%3};" \
        : "+f"((d)[0]), "+f"((d)[1]), "+f"((d)[2]), "+f"((d)[3]) \
        : "r"((a)[0]), "r"((a)[1]), "r"((a)[2]), "r"((a)[3]), \
          "r"((b)[0]), "r"((b)[1]))

// ---------------------------------------------------------------------------
// bf16 hi/lo split helper
// ---------------------------------------------------------------------------
__device__ __forceinline__ void split4(float4 v, __nv_bfloat16* ph, __nv_bfloat16* pl) {
    __nv_bfloat162 h0 = __floats2bfloat162_rn(v.x, v.y);
    __nv_bfloat162 h1 = __floats2bfloat162_rn(v.z, v.w);
    float2 f0 = __bfloat1622float2(h0);
    float2 f1 = __bfloat1622float2(h1);
    __nv_bfloat162 l0 = __floats2bfloat162_rn(v.x - f0.x, v.y - f0.y);
    __nv_bfloat162 l1 = __floats2bfloat162_rn(v.z - f1.x, v.w - f1.y);
    *(__nv_bfloat162*)(ph)     = h0;
    *(__nv_bfloat162*)(ph + 2) = h1;
    *(__nv_bfloat162*)(pl)     = l0;
    *(__nv_bfloat162*)(pl + 2) = l1;
}

// ---------------------------------------------------------------------------
// Graph preprocessing
// ---------------------------------------------------------------------------
__global__ void k_zero() {
    int i = blockIdx.x * blockDim.x + threadIdx.x;
    if (i < NN) { g_deg[i] = 0; g_cursor[i] = 0; }
}

__global__ void k_hist(const int* __restrict__ ei) {
    int e = blockIdx.x * blockDim.x + threadIdx.x;
    if (e < EE) atomicAdd(&g_deg[ei[EE + e]], 1);
}

__global__ void k_scan1() {
    __shared__ int sh[1024];
    int i = blockIdx.x * 1024 + threadIdx.x;
    int v = (i < NN) ? g_deg[i] : 0;
    if (i < NN) g_dinv[i] = rsqrtf((float)v + 1.0f);
    sh[threadIdx.x] = v;
    __syncthreads();
    #pragma unroll
    for (int off = 1; off < 1024; off <<= 1) {
        int t = (threadIdx.x >= off) ? sh[threadIdx.x - off] : 0;
        __syncthreads();
        sh[threadIdx.x] += t;
        __syncthreads();
    }
    if (i < NN) g_rowptr[i] = sh[threadIdx.x] - v;
    if (threadIdx.x == 1023) g_bsum[blockIdx.x] = sh[1023];
}

__global__ void k_scan2() {
    __shared__ int sh[128];
    const int NB = (NN + 1023) / 1024;
    int v = (threadIdx.x < NB) ? g_bsum[threadIdx.x] : 0;
    sh[threadIdx.x] = v;
    __syncthreads();
    #pragma unroll
    for (int off = 1; off < 128; off <<= 1) {
        int t = (threadIdx.x >= off) ? sh[threadIdx.x - off] : 0;
        __syncthreads();
        sh[threadIdx.x] += t;
        __syncthreads();
    }
    g_bsum[threadIdx.x] = sh[threadIdx.x] - v;
}

__global__ void k_scan3() {
    int i = blockIdx.x * 1024 + threadIdx.x;
    if (i < NN) g_rowptr[i] += g_bsum[blockIdx.x];
    if (i == 0) g_rowptr[NN] = EE;
}

__global__ void k_scatter(const int* __restrict__ ei) {
    int e = blockIdx.x * blockDim.x + threadIdx.x;
    if (e >= EE) return;
    int s = ei[e];
    int d = ei[EE + e];
    int pos = g_rowptr[d] + atomicAdd(&g_cursor[d], 1);
    g_srcs[pos]  = s;
    g_norms[pos] = g_dinv[s] * g_dinv[d];
}

// ---------------------------------------------------------------------------
// Weight transpose + bf16 split: Wh/Wl[n*256+k] from W[k*256+n]
// ---------------------------------------------------------------------------
__global__ void k_wsplit(const float* __restrict__ W1, const float* __restrict__ W2,
                         const float* __restrict__ W3) {
    int idx = blockIdx.x * 256 + threadIdx.x;   // 0..196607
    int l = idx >> 16;
    int r = idx & 65535;
    int k = r >> 8, n = r & 255;
    const float* W = (l == 0) ? W1 : ((l == 1) ? W2 : W3);
    float v = W[k * 256 + n];
    __nv_bfloat16 hi = __float2bfloat16(v);
    g_wh[l * 65536 + n * 256 + k] = hi;
    g_wl[l * 65536 + n * 256 + k] = __float2bfloat16(v - __bfloat162float(hi));
}

// x (fp32) -> g_ah/g_al (bf16 hi/lo)
__global__ void k_xsplit(const float* __restrict__ x) {
    size_t i = (size_t)blockIdx.x * blockDim.x + threadIdx.x;   // float4 index
    if (i >= (size_t)NN * 64) return;
    float4 v = ((const float4*)x)[i];
    split4(v, g_ah + i * 4, g_al + i * 4);
}

// ---------------------------------------------------------------------------
// Tensor GEMM via mma.sync (bf16 split 3-term):
//   g_gout[M x 256] = (Ah+Al)[M x 256] @ W[256 x 256]
// CTA tile 128x128, 8 warps (4m x 2n), warp tile 32x64, K-step 16.
// 4-stage cp.async ring, ONE __syncthreads per K-step.
// Stage layout (bytes, per stage of 24576):
//   Ah @ +0, Al @ +6144, Bh @ +12288, Bl @ +18432; rows padded to 48 B.
// Grid: (2, 782) -> N-split fastest so sibling CTAs share A tiles in L2.
// ---------------------------------------------------------------------------
#define MG_STAGE 24576u
#define MG_SMEM  98304

__global__ void __launch_bounds__(256, 2) k_mgemm(int lidx) {
    extern __shared__ char smem[];
    const uint32_t sb = smem_u32(smem);

    const int tid  = threadIdx.x;
    const int wid  = tid >> 5;
    const int lane = tid & 31;
    const int wm   = wid >> 1;          // 0..3
    const int wn   = wid & 1;           // 0..1
    const int    ncol0 = blockIdx.x * 128;
    const size_t row0  = (size_t)blockIdx.y * 128;

    const __nv_bfloat16* __restrict__ Wh = g_wh + (size_t)lidx * 65536;
    const __nv_bfloat16* __restrict__ Wl = g_wl + (size_t)lidx * 65536;

    // global-load thread mapping (per k-step)
    const int gr = tid >> 1;            // 0..127 (row / ncol)
    const int gk = (tid & 1) * 8;       // bf16 k offset within 16
    const size_t gA = (row0 + gr) * 256 + gk;
    const size_t gB = ((size_t)(ncol0 + gr)) * 256 + gk;
    const uint32_t sOff = (uint32_t)(gr * 48 + gk * 2);

    // ldmatrix per-thread offsets
    const int lr = lane & 7;
    const uint32_t offA = (uint32_t)((wm * 32 + lr + ((lane >> 3) & 1) * 8) * 48
                                     + ((lane >> 4) & 1) * 16);
    const uint32_t offB = (uint32_t)((wn * 64 + lr + ((lane >> 4) & 1) * 8) * 48
                                     + ((lane >> 3) & 1) * 16);

    float acc[2][8][4];
    #pragma unroll
    for (int i = 0; i < 2; i++)
        #pragma unroll
        for (int j = 0; j < 8; j++)
            #pragma unroll
            for (int q = 0; q < 4; q++) acc[i][j][q] = 0.f;

    // prologue: fill stages 0..2
    #pragma unroll
    for (int p = 0; p < 3; p++) {
        const uint32_t bo = (uint32_t)p * MG_STAGE;
        const size_t kk = (size_t)p * 16;
        CP16(sb + bo + sOff,          g_ah + gA + kk);
        CP16(sb + bo + 6144u + sOff,  g_al + gA + kk);
        CP16(sb + bo + 12288u + sOff, Wh + gB + kk);
        CP16(sb + bo + 18432u + sOff, Wl + gB + kk);
        CP_COMMIT();
    }

    for (int c = 0; c < 16; c++) {
        CP_WAIT2();
        __syncthreads();

        // issue loads for stage c+3 (overwrites the buffer read at iter c-1;
        // safe: all iter c-1 reads completed before this sync)
        if (c + 3 < 16) {
            const uint32_t bo = (uint32_t)((c + 3) & 3) * MG_STAGE;
            const size_t kk = (size_t)(c + 3) * 16;
            CP16(sb + bo + sOff,          g_ah + gA + kk);
            CP16(sb + bo + 6144u + sOff,  g_al + gA + kk);
            CP16(sb + bo + 12288u + sOff, Wh + gB + kk);
            CP16(sb + bo + 18432u + sOff, Wl + gB + kk);
        }
        CP_COMMIT();   // empty group near the tail keeps accounting uniform

        const uint32_t base  = sb + (uint32_t)(c & 3) * MG_STAGE;
        const uint32_t aBase = base + offA;
        const uint32_t bBase = base + 12288u + offB;

        uint32_t ah[2][4], al[2][4], bh[8][2], bl[8][2];
        #pragma unroll
        for (int mi = 0; mi < 2; mi++) {
            LDSM4(ah[mi][0], ah[mi][1], ah[mi][2], ah[mi][3], aBase + mi * 768u);
            LDSM4(al[mi][0], al[mi][1], al[mi][2], al[mi][3], aBase + 6144u + mi * 768u);
        }
        #pragma unroll
        for (int j = 0; j < 4; j++) {
            uint32_t t0, t1, t2, t3;
            LDSM4(t0, t1, t2, t3, bBase + j * 768u);
            bh[2 * j][0] = t0; bh[2 * j][1] = t1;
            bh[2 * j + 1][0] = t2; bh[2 * j + 1][1] = t3;
            LDSM4(t0, t1, t2, t3, bBase + 6144u + j * 768u);
            bl[2 * j][0] = t0; bl[2 * j][1] = t1;
            bl[2 * j + 1][0] = t2; bl[2 * j + 1][1] = t3;
        }

        #pragma unroll
        for (int mi = 0; mi < 2; mi++)
            #pragma unroll
            for (int nj = 0; nj < 8; nj++) {
                MMA16816(acc[mi][nj], ah[mi], bh[nj]);
                MMA16816(acc[mi][nj], ah[mi], bl[nj]);
                MMA16816(acc[mi][nj], al[mi], bh[nj]);
            }
    }

    // epilogue
    #pragma unroll
    for (int mi = 0; mi < 2; mi++) {
        const size_t r0 = row0 + wm * 32 + mi * 16 + (lane >> 2);
        const int cc0 = ncol0 + wn * 64 + (lane & 3) * 2;
        #pragma unroll
        for (int nj = 0; nj < 8; nj++) {
            const int cc = cc0 + nj * 8;
            if (r0 < NN)
                *(float2*)&g_gout[r0 * 256 + cc] =
                    make_float2(acc[mi][nj][0], acc[mi][nj][1]);
            if (r0 + 8 < NN)
                *(float2*)&g_gout[(r0 + 8) * 256 + cc] =
                    make_float2(acc[mi][nj][2], acc[mi][nj][3]);
        }
    }
}

// ---------------------------------------------------------------------------
// SpMM (F=256): agg = sum_e norm * H[src] + dinv^2 * H[n] + bias, relu,
// writes bf16 hi/lo splits for the next GEMM. H = g_gout (fp32).
// ---------------------------------------------------------------------------
__global__ void __launch_bounds__(256) k_spmm256(const float* __restrict__ bias) {
    const float* __restrict__ H = g_gout;

    int warp = threadIdx.x >> 5;
    int lane = threadIdx.x & 31;
    int node = blockIdx.x * 8 + warp;
    if (node >= NN) return;

    int beg = g_rowptr[node];
    int end = g_rowptr[node + 1];

    float4 acc0 = make_float4(0.f, 0.f, 0.f, 0.f);
    float4 acc1 = make_float4(0.f, 0.f, 0.f, 0.f);

    int e = beg;
    for (; e + 1 < end; e += 2) {
        int   s0 = g_srcs[e],     s1 = g_srcs[e + 1];
        float w0 = g_norms[e],    w1 = g_norms[e + 1];
        const float4* hp0 = (const float4*)(H + (size_t)s0 * 256);
        const float4* hp1 = (const float4*)(H + (size_t)s1 * 256);
        float4 a0 = hp0[lane];
        float4 b0 = hp0[lane + 32];
        float4 a1 = hp1[lane];
        float4 b1 = hp1[lane + 32];
        acc0.x += w0 * a0.x + w1 * a1.x; acc0.y += w0 * a0.y + w1 * a1.y;
        acc0.z += w0 * a0.z + w1 * a1.z; acc0.w += w0 * a0.w + w1 * a1.w;
        acc1.x += w0 * b0.x + w1 * b1.x; acc1.y += w0 * b0.y + w1 * b1.y;
        acc1.z += w0 * b0.z + w1 * b1.z; acc1.w += w0 * b0.w + w1 * b1.w;
    }
    for (; e < end; e++) {
        int   s = g_srcs[e];
        float w = g_norms[e];
        const float4* hp = (const float4*)(H + (size_t)s * 256);
        float4 a = hp[lane];
        float4 b = hp[lane + 32];
        acc0.x += w * a.x; acc0.y += w * a.y; acc0.z += w * a.z; acc0.w += w * a.w;
        acc1.x += w * b.x; acc1.y += w * b.y; acc1.z += w * b.z; acc1.w += w * b.w;
    }

    float di = g_dinv[node];
    float w2 = di * di;
    {
        const float4* hp = (const float4*)(H + (size_t)node * 256);
        float4 a = hp[lane];
        float4 b = hp[lane + 32];
        acc0.x += w2 * a.x; acc0.y += w2 * a.y; acc0.z += w2 * a.z; acc0.w += w2 * a.w;
        acc1.x += w2 * b.x; acc1.y += w2 * b.y; acc1.z += w2 * b.z; acc1.w += w2 * b.w;
    }

    const float4* bb = (const float4*)bias;
    float4 b0 = bb[lane];
    float4 b1 = bb[lane + 32];
    acc0.x = fmaxf(acc0.x + b0.x, 0.f); acc0.y = fmaxf(acc0.y + b0.y, 0.f);
    acc0.z = fmaxf(acc0.z + b0.z, 0.f); acc0.w = fmaxf(acc0.w + b0.w, 0.f);
    acc1.x = fmaxf(acc1.x + b1.x, 0.f); acc1.y = fmaxf(acc1.y + b1.y, 0.f);
    acc1.w = fmaxf(acc1.w + b1.w, 0.f); acc1.z = fmaxf(acc1.z + b1.z, 0.f);

    size_t base = (size_t)node * 256 + lane * 4;
    split4(acc0, g_ah + base,       g_al + base);
    split4(acc1, g_ah + base + 128, g_al + base + 128);
}

// ---------------------------------------------------------------------------
// GEMM (N=16): g_gout[M x 16] = (g_ah+g_al)[M x 256] @ W4[256 x 16]
// ---------------------------------------------------------------------------
__global__ void __launch_bounds__(256) k_gemm16(const float* __restrict__ W) {
    __shared__ float Ws[256 * 16];
    for (int i = threadIdx.x; i < 256 * 16; i += 256) Ws[i] = W[i];
    __syncthreads();

    int r = blockIdx.x * 16 + (threadIdx.x >> 4);
    int c = threadIdx.x & 15;
    if (r >= NN) return;

    const __nv_bfloat162* ah = (const __nv_bfloat162*)(g_ah + (size_t)r * 256);
    const __nv_bfloat162* al = (const __nv_bfloat162*)(g_al + (size_t)r * 256);
    float acc = 0.f;
    #pragma unroll 16
    for (int k2 = 0; k2 < 128; k2++) {
        float2 h = __bfloat1622float2(ah[k2]);
        float2 l = __bfloat1622float2(al[k2]);
        acc += (h.x + l.x) * Ws[(2 * k2) * 16 + c];
        acc += (h.y + l.y) * Ws[(2 * k2 + 1) * 16 + c];
    }
    g_gout[(size_t)r * 16 + c] = acc;
}

// ---------------------------------------------------------------------------
// SpMM (F=16) + bias + log_softmax -> final output
// ---------------------------------------------------------------------------
__global__ void __launch_bounds__(256) k_spmm16(const float* __restrict__ bias,
                                               float* __restrict__ out) {
    const float* __restrict__ H = g_gout;

    int warp = threadIdx.x >> 5;
    int lane = threadIdx.x & 31;
    int node = blockIdx.x * 8 + warp;
    if (node >= NN) return;

    int f = lane & 15;
    int beg = g_rowptr[node];
    int end = g_rowptr[node + 1];

    float acc = 0.f;
    for (int e = beg; e < end; e++) {
        int s = g_srcs[e];
        acc += g_norms[e] * H[(size_t)s * 16 + f];
    }
    float di = g_dinv[node];
    acc += di * di * H[(size_t)node * 16 + f];
    acc += bias[f];

    float m = acc;
    #pragma unroll
    for (int o = 8; o > 0; o >>= 1)
        m = fmaxf(m, __shfl_xor_sync(0xffffffffu, m, o, 16));
    float ex = expf(acc - m);
    float s = ex;
    #pragma unroll
    for (int o = 8; o > 0; o >>= 1)
        s += __shfl_xor_sync(0xffffffffu, s, o, 16);

    if (lane < 16)
        out[(size_t)node * 16 + f] = (acc - m) - logf(s);
}

// ---------------------------------------------------------------------------
// Launcher — single stream (stream fork removed; suspected capture hazard)
// ---------------------------------------------------------------------------
extern "C" void kernel_launch(void* const* d_in, const int* in_sizes, int n_in,
                              void* d_out, int out_size)
{
    const float* x  = (const float*)d_in[0];
    const int*   ei = (const int*)  d_in[1];
    const float* W1 = (const float*)d_in[2];
    const float* b1 = (const float*)d_in[3];
    const float* W2 = (const float*)d_in[4];
    const float* b2 = (const float*)d_in[5];
    const float* W3 = (const float*)d_in[6];
    const float* b3 = (const float*)d_in[7];
    const float* W4 = (const float*)d_in[8];
    const float* b4 = (const float*)d_in[9];
    float* out = (float*)d_out;

    static int s_attr_done = 0;
    if (!s_attr_done) {
        cudaFuncSetAttribute(k_mgemm, cudaFuncAttributeMaxDynamicSharedMemorySize, MG_SMEM);
        s_attr_done = 1;
    }

    const int NB_SCAN = (NN + 1023) / 1024;   // 98

    // graph preprocessing
    k_zero   <<<(NN + 255) / 256, 256>>>();
    k_hist   <<<(EE + 255) / 256, 256>>>(ei);
    k_scan1  <<<NB_SCAN, 1024>>>();
    k_scan2  <<<1, 128>>>();
    k_scan3  <<<NB_SCAN, 1024>>>();
    k_scatter<<<(EE + 255) / 256, 256>>>(ei);

    // operand prep
    k_wsplit <<<768, 256>>>(W1, W2, W3);
    k_xsplit <<<(NN * 64 + 255) / 256, 256>>>(x);

    dim3 ggrid(2, MPAD / 128);                // N-split fastest (L2 reuse of A)
    const int sgrid = (NN + 7) / 8;           // 12500

    // layer 1
    k_mgemm  <<<ggrid, 256, MG_SMEM>>>(0);
    k_spmm256<<<sgrid, 256>>>(b1);
    // layer 2
    k_mgemm  <<<ggrid, 256, MG_SMEM>>>(1);
    k_spmm256<<<sgrid, 256>>>(b2);
    // layer 3
    k_mgemm  <<<ggrid, 256, MG_SMEM>>>(2);
    k_spmm256<<<sgrid, 256>>>(b3);
    // layer 4
    k_gemm16 <<<(NN + 15) / 16, 256>>>(W4);
    k_spmm16 <<<sgrid, 256>>>(b4, out);
}